// round 11
// baseline (speedup 1.0000x reference)
#include <cuda_runtime.h>
#include <cuda_bf16.h>
#include <cstdint>

// Problem constants
#define NPTS 4096
#define DIM  64
#define TS   128          // block tile (i and j)
#define THREADS 256       // 8 warps; warp w -> rows w*16..w*16+15
#define IBLOCKS (NPTS/TS) // 32
#define JSPLIT 32         // one j-tile per block -> 1024 blocks
#define ROWP 68           // bf16 row stride (64 + 4 pad -> conflict-free)
#define TILE_BYTES (TS * ROWP * 2)        // 17408
#define SMEM_BYTES (4 * TILE_BYTES + 3 * TS * 4)  // 71168

// Scratch (device global -- no allocation allowed)
__device__ float g_part[JSPLIT * NPTS];

__device__ __forceinline__ void mma_bf16(float d[4],
                                         uint32_t a0, uint32_t a1, uint32_t a2, uint32_t a3,
                                         uint32_t b0, uint32_t b1) {
    asm volatile(
        "mma.sync.aligned.m16n8k16.row.col.f32.bf16.bf16.f32 "
        "{%0,%1,%2,%3}, {%4,%5,%6,%7}, {%8,%9}, {%0,%1,%2,%3};"
        : "+f"(d[0]), "+f"(d[1]), "+f"(d[2]), "+f"(d[3])
        : "r"(a0), "r"(a1), "r"(a2), "r"(a3), "r"(b0), "r"(b1));
}

// ---------- kernel 1: RBF kernel * alpha via split-bf16 tensor cores ----------
__global__ __launch_bounds__(THREADS, 2)
void svr_main(const float* __restrict__ feat, const float* __restrict__ alpha) {
    extern __shared__ char smem[];
    __nv_bfloat16* sih = (__nv_bfloat16*)smem;                     // [TS][ROWP] i hi
    __nv_bfloat16* sil = (__nv_bfloat16*)(smem + TILE_BYTES);      // i lo
    __nv_bfloat16* sjh = (__nv_bfloat16*)(smem + 2 * TILE_BYTES);  // j hi
    __nv_bfloat16* sjl = (__nv_bfloat16*)(smem + 3 * TILE_BYTES);  // j lo
    float* salpha = (float*)(smem + 4 * TILE_BYTES);               // [TS]
    float* ssqi   = salpha + TS;                                   // [TS]
    float* ssqj   = ssqi + TS;                                     // [TS]

    const int tid  = threadIdx.x;
    const int w    = tid >> 5;
    const int lane = tid & 31;
    const int g    = lane >> 2;   // 0..7
    const int tig  = lane & 3;    // 0..3
    const int ibase = blockIdx.x * TS;
    const int jbase = blockIdx.y * TS;

    const float4* featv = reinterpret_cast<const float4*>(feat);

    // ---- Stage + split-convert i and j tiles (fp32 -> hi/lo bf16) ----
#pragma unroll 1
    for (int t = 0; t < 2; t++) {
        const int  base  = t ? jbase : ibase;
        __nv_bfloat16* dh = t ? sjh : sih;
        __nv_bfloat16* dl = t ? sjl : sil;
        for (int idx = tid; idx < TS * (DIM / 4); idx += THREADS) {
            int row = idx >> 4;
            int k4  = idx & 15;
            float4 v = featv[(base + row) * (DIM / 4) + k4];
            __nv_bfloat16 hx = __float2bfloat16(v.x);
            __nv_bfloat16 hy = __float2bfloat16(v.y);
            __nv_bfloat16 hz = __float2bfloat16(v.z);
            __nv_bfloat16 hw = __float2bfloat16(v.w);
            __nv_bfloat16 lx = __float2bfloat16(v.x - __bfloat162float(hx));
            __nv_bfloat16 ly = __float2bfloat16(v.y - __bfloat162float(hy));
            __nv_bfloat16 lz = __float2bfloat16(v.z - __bfloat162float(hz));
            __nv_bfloat16 lw = __float2bfloat16(v.w - __bfloat162float(hw));
            int off = row * ROWP + k4 * 4;
            *reinterpret_cast<__nv_bfloat162*>(dh + off)     = __nv_bfloat162(hx, hy);
            *reinterpret_cast<__nv_bfloat162*>(dh + off + 2) = __nv_bfloat162(hz, hw);
            *reinterpret_cast<__nv_bfloat162*>(dl + off)     = __nv_bfloat162(lx, ly);
            *reinterpret_cast<__nv_bfloat162*>(dl + off + 2) = __nv_bfloat162(lz, lw);
        }
    }

    // ---- Exact fp32 squared norms from gmem (L2-hot) + alpha ----
    {
        int r = tid & (TS - 1);
        const float4* fr = featv + ((tid < TS ? ibase : jbase) + r) * (DIM / 4);
        float s = 0.f;
#pragma unroll
        for (int k4 = 0; k4 < DIM / 4; k4++) {
            float4 v = fr[k4];
            s = fmaf(v.x, v.x, s);
            s = fmaf(v.y, v.y, s);
            s = fmaf(v.z, v.z, s);
            s = fmaf(v.w, v.w, s);
        }
        if (tid < TS) ssqi[r] = s;
        else { ssqj[r] = s; salpha[r] = alpha[jbase + r]; }
    }
    __syncthreads();

    // ---- MMA mainloop: warp tile 16 x 128, D[16 n-tiles][4] fp32 ----
    float d[16][4];
#pragma unroll
    for (int nt = 0; nt < 16; nt++)
#pragma unroll
        for (int c = 0; c < 4; c++) d[nt][c] = 0.f;

    const int r0 = w * 16 + g;   // A rows r0, r0+8
#pragma unroll
    for (int kc = 0; kc < 4; kc++) {
        const int k0 = kc * 16;
        const uint32_t* ah0 = reinterpret_cast<const uint32_t*>(sih + r0 * ROWP + k0 + 2 * tig);
        const uint32_t* ah1 = reinterpret_cast<const uint32_t*>(sih + (r0 + 8) * ROWP + k0 + 2 * tig);
        const uint32_t* al0 = reinterpret_cast<const uint32_t*>(sil + r0 * ROWP + k0 + 2 * tig);
        const uint32_t* al1 = reinterpret_cast<const uint32_t*>(sil + (r0 + 8) * ROWP + k0 + 2 * tig);
        uint32_t Ah[4] = {ah0[0], ah1[0], ah0[4], ah1[4]};
        uint32_t Al[4] = {al0[0], al1[0], al0[4], al1[4]};
#pragma unroll
        for (int nt = 0; nt < 16; nt++) {
            const uint32_t* bh = reinterpret_cast<const uint32_t*>(
                sjh + (nt * 8 + g) * ROWP + k0 + 2 * tig);
            const uint32_t* bl = reinterpret_cast<const uint32_t*>(
                sjl + (nt * 8 + g) * ROWP + k0 + 2 * tig);
            uint32_t Bh0 = bh[0], Bh1 = bh[4];
            uint32_t Bl0 = bl[0], Bl1 = bl[4];
            mma_bf16(d[nt], Ah[0], Ah[1], Ah[2], Ah[3], Bh0, Bh1);  // hi*hi
            mma_bf16(d[nt], Ah[0], Ah[1], Ah[2], Ah[3], Bl0, Bl1);  // hi*lo
            mma_bf16(d[nt], Al[0], Al[1], Al[2], Al[3], Bh0, Bh1);  // lo*hi
        }
    }

    // ---- Epilogue: d2 -> exp -> weighted row sums ----
    const float inv2s2 = 0.02f;  // 1/(2*sigma^2), sigma=5
    const float sqi0 = ssqi[r0];
    const float sqi1 = ssqi[r0 + 8];
    float acc0 = 0.f, acc1 = 0.f;
#pragma unroll
    for (int nt = 0; nt < 16; nt++) {
        int jc = nt * 8 + 2 * tig;
        float sj0 = ssqj[jc],     sj1 = ssqj[jc + 1];
        float a0  = salpha[jc],   a1  = salpha[jc + 1];
        float x00 = fmaxf(fmaf(-2.f, d[nt][0], sqi0 + sj0), 0.f);
        float x01 = fmaxf(fmaf(-2.f, d[nt][1], sqi0 + sj1), 0.f);
        float x10 = fmaxf(fmaf(-2.f, d[nt][2], sqi1 + sj0), 0.f);
        float x11 = fmaxf(fmaf(-2.f, d[nt][3], sqi1 + sj1), 0.f);
        acc0 = fmaf(__expf(-inv2s2 * x00), a0, acc0);
        acc0 = fmaf(__expf(-inv2s2 * x01), a1, acc0);
        acc1 = fmaf(__expf(-inv2s2 * x10), a0, acc1);
        acc1 = fmaf(__expf(-inv2s2 * x11), a1, acc1);
    }

    // Reduce over tig within each quad (lanes 4g+tig share output rows)
    acc0 += __shfl_xor_sync(0xffffffffu, acc0, 1);
    acc0 += __shfl_xor_sync(0xffffffffu, acc0, 2);
    acc1 += __shfl_xor_sync(0xffffffffu, acc1, 1);
    acc1 += __shfl_xor_sync(0xffffffffu, acc1, 2);
    if (tig == 0) {
        g_part[blockIdx.y * NPTS + ibase + r0]     = acc0;
        g_part[blockIdx.y * NPTS + ibase + r0 + 8] = acc1;
    }
}

// ---------- kernel 2: reduce j-splits + bias ----------
__global__ void svr_final(const float* __restrict__ bias, float* __restrict__ out) {
    int i = blockIdx.x * blockDim.x + threadIdx.x;
    if (i < NPTS) {
        float s = bias[0];
#pragma unroll
        for (int p = 0; p < JSPLIT; p++) s += g_part[p * NPTS + i];
        out[i] = s;
    }
}

extern "C" void kernel_launch(void* const* d_in, const int* in_sizes, int n_in,
                              void* d_out, int out_size) {
    const float* feat  = (const float*)d_in[0];
    const float* alpha = (const float*)d_in[1];
    const float* bias  = (const float*)d_in[2];
    float* out = (float*)d_out;

    cudaFuncSetAttribute(svr_main, cudaFuncAttributeMaxDynamicSharedMemorySize,
                         SMEM_BYTES);

    svr_main<<<dim3(IBLOCKS, JSPLIT), THREADS, SMEM_BYTES>>>(feat, alpha);
    svr_final<<<NPTS / 256, 256>>>(bias, out);
}